// round 8
// baseline (speedup 1.0000x reference)
#include <cuda_runtime.h>
#include <cuda_bf16.h>
#include <math.h>
#include <stdint.h>

#define DM    1024
#define NIMU  72
#define NOUT  864
#define NPAD  896
#define KC    64
#define NCHT  48          // 3 * (DM/KC): virtual K = 3072
#define TILEB 16384       // 128 rows x 128B
#define STAGEB (2 * TILEB)  // A tile + B tile

__device__ __nv_bfloat16 g_xn_hi[4096 * DM];
__device__ __nv_bfloat16 g_xn_lo[4096 * DM];
__device__ __nv_bfloat16 g_wT_hi[NPAD * DM];
__device__ __nv_bfloat16 g_wT_lo[NPAD * DM];
__device__ float         g_p[4096 * NPAD];
__device__ float         g_osc[4096 * NIMU * 8];

__device__ __forceinline__ uint32_t smem_u32(const void* p) {
    uint32_t a;
    asm("{ .reg .u64 t; cvta.to.shared.u64 t, %1; cvt.u32.u64 %0, t; }" : "=r"(a) : "l"(p));
    return a;
}
#define SWZ128(o) ((o) ^ (((o) >> 3) & 0x70))

__device__ __forceinline__ void cp16(uint32_t s, const void* g) {
    asm volatile("cp.async.cg.shared.global [%0], [%1], 16;"
                 :: "r"(s), "l"(__cvta_generic_to_global(g)) : "memory");
}
#define CP_COMMIT() asm volatile("cp.async.commit_group;" ::: "memory")
#define CP_WAIT(n)  asm volatile("cp.async.wait_group %0;" :: "n"(n) : "memory")

#define LDSM4(r0, r1, r2, r3, a) \
    asm volatile("ldmatrix.sync.aligned.m8n8.x4.shared.b16 {%0,%1,%2,%3}, [%4];" \
                 : "=r"(r0), "=r"(r1), "=r"(r2), "=r"(r3) : "r"(a))

#define MMA(d, a, b) \
    asm volatile("mma.sync.aligned.m16n8k16.row.col.f32.bf16.bf16.f32 " \
                 "{%0,%1,%2,%3}, {%4,%5,%6,%7}, {%8,%9}, {%0,%1,%2,%3};" \
                 : "+f"((d)[0]), "+f"((d)[1]), "+f"((d)[2]), "+f"((d)[3]) \
                 : "r"((a)[0]), "r"((a)[1]), "r"((a)[2]), "r"((a)[3]), \
                   "r"((b)[0]), "r"((b)[1]))

// packed f32x2 ops (sm_100+)
#define ADDX2(d, a, b) asm("add.rn.f32x2 %0, %1, %2;" : "=l"(d) : "l"(a), "l"(b))
#define MULX2(d, a, b) asm("mul.rn.f32x2 %0, %1, %2;" : "=l"(d) : "l"(a), "l"(b))
#define FMAX2(d, a, b, c) asm("fma.rn.f32x2 %0, %1, %2, %3;" : "=l"(d) : "l"(a), "l"(b), "l"(c))
__device__ __forceinline__ unsigned long long packf2(float lo, float hi) {
    unsigned long long r;
    asm("mov.b64 %0, {%1, %2};" : "=l"(r) : "f"(lo), "f"(hi));
    return r;
}
__device__ __forceinline__ void unpackf2(float& lo, float& hi, unsigned long long v) {
    asm("mov.b64 {%0, %1}, %2;" : "=f"(lo), "=f"(hi) : "l"(v));
}

// ---------------- LayerNorm + split ----------------
__global__ __launch_bounds__(256) void ln_kernel(const float* __restrict__ x,
                                                 const float* __restrict__ gamma,
                                                 const float* __restrict__ beta) {
    int s = blockIdx.x, tid = threadIdx.x;
    const float4* xr = (const float4*)(x + (size_t)s * DM);
    float4 v = xr[tid];
    float sum = v.x + v.y + v.z + v.w;
    float sq  = v.x*v.x + v.y*v.y + v.z*v.z + v.w*v.w;
#pragma unroll
    for (int o = 16; o > 0; o >>= 1) {
        sum += __shfl_xor_sync(0xffffffffu, sum, o);
        sq  += __shfl_xor_sync(0xffffffffu, sq,  o);
    }
    __shared__ float ssum[8], ssq[8], s_mu, s_rs;
    int wid = tid >> 5, lane = tid & 31;
    if (lane == 0) { ssum[wid] = sum; ssq[wid] = sq; }
    __syncthreads();
    if (tid == 0) {
        float ts = 0.f, tq = 0.f;
#pragma unroll
        for (int i = 0; i < 8; i++) { ts += ssum[i]; tq += ssq[i]; }
        float mu  = ts * (1.0f / DM);
        float var = tq * (1.0f / DM) - mu * mu;
        s_mu = mu; s_rs = rsqrtf(var + 1e-5f);
    }
    __syncthreads();
    float mu = s_mu, rs = s_rs;
    size_t base = (size_t)s * DM + (size_t)tid * 4;
    float xv[4] = {v.x, v.y, v.z, v.w};
#pragma unroll
    for (int j = 0; j < 4; j++) {
        int c = tid * 4 + j;
        float xn = (xv[j] - mu) * rs * gamma[c] + beta[c];
        __nv_bfloat16 hi = __float2bfloat16(xn);
        g_xn_hi[base + j] = hi;
        g_xn_lo[base + j] = __float2bfloat16(xn - __bfloat162float(hi));
    }
}

// ---------------- W transpose+pad+split via smem tiles ----------------
// grid: (DM/32, NPAD/32), block 256. Read W[k][n] coalesced, write g_wT[n][k] coalesced.
__global__ __launch_bounds__(256) void wsplit_kernel(const float* __restrict__ W) {
    __shared__ float tile[32][33];
    int k0 = blockIdx.x * 32, n0 = blockIdx.y * 32;
    int tx = threadIdx.x & 31, ty = threadIdx.x >> 5;   // 32 x 8
#pragma unroll
    for (int i = 0; i < 4; i++) {
        int k = k0 + ty + i * 8, n = n0 + tx;
        tile[ty + i * 8][tx] = (n < NOUT) ? W[k * NOUT + n] : 0.0f;
    }
    __syncthreads();
#pragma unroll
    for (int i = 0; i < 4; i++) {
        int n = n0 + ty + i * 8, k = k0 + tx;
        float w = tile[tx][ty + i * 8];
        __nv_bfloat16 hi = __float2bfloat16(w);
        size_t idx = (size_t)n * DM + k;
        g_wT_hi[idx] = hi;
        g_wT_lo[idx] = __float2bfloat16(w - __bfloat162float(hi));
    }
}

// ---------------- single-pass K=3072 bf16 GEMM ----------------
__global__ __launch_bounds__(512, 2) void gemm_kernel() {
    extern __shared__ __align__(1024) char smem[];
    uint32_t sb = smem_u32(smem);
    int tid = threadIdx.x, wid = tid >> 5, lane = tid & 31;
    int bm = blockIdx.x * 128, bn = blockIdx.y * 128;
    int wm = wid & 3, wn = wid >> 2;   // 4x4 warps, 32x32 tiles

    // stage loader: 2 tiles x 1024 16B-segs, 4 cp16 per thread
    auto load_stage = [&](int kc, int buf) {
        int phase = kc >> 4;
        const __nv_bfloat16* Asrc = (phase == 1) ? g_xn_lo : g_xn_hi;
        const __nv_bfloat16* Bsrc = (phase == 2) ? g_wT_lo : g_wT_hi;
        int ko = (kc & 15) * KC;
        uint32_t base = sb + (uint32_t)buf * STAGEB;
#pragma unroll
        for (int i = 0; i < 2; i++) {
            int seg = tid + i * 512;
            int r = seg >> 3, c = seg & 7;
            uint32_t sw = SWZ128(r * 128 + c * 16);
            cp16(base + sw,         Asrc + (size_t)(bm + r) * DM + ko + c * 8);
            cp16(base + TILEB + sw, Bsrc + (size_t)(bn + r) * DM + ko + c * 8);
        }
        CP_COMMIT();
    };

    load_stage(0, 0);
    load_stage(1, 1);

    float acc[2][4][4];
#pragma unroll
    for (int i = 0; i < 2; i++)
#pragma unroll
        for (int j = 0; j < 4; j++)
#pragma unroll
            for (int q = 0; q < 4; q++) acc[i][j][q] = 0.0f;

    int a_m = (lane & 7) + ((lane >> 3) & 1) * 8;
    int a_k = (lane >> 4) * 8;
    int b_n = (lane & 7) + ((lane >> 4) & 1) * 8;
    int b_k = ((lane >> 3) & 1) * 8;

    for (int kc = 0; kc < NCHT; kc++) {
        if (kc + 2 < NCHT) { load_stage(kc + 2, (kc + 2) % 3); CP_WAIT(2); }
        else               { CP_WAIT(0); }
        __syncthreads();
        uint32_t st = sb + (uint32_t)(kc % 3) * STAGEB;
#pragma unroll
        for (int ks = 0; ks < 4; ks++) {
            uint32_t ah[2][4], bb[4][2];
#pragma unroll
            for (int i = 0; i < 2; i++) {
                uint32_t ad = st + SWZ128((wm * 32 + i * 16 + a_m) * 128 + (ks * 16 + a_k) * 2);
                LDSM4(ah[i][0], ah[i][1], ah[i][2], ah[i][3], ad);
            }
#pragma unroll
            for (int jj = 0; jj < 2; jj++) {
                uint32_t bd = st + TILEB + SWZ128((wn * 32 + jj * 16 + b_n) * 128 + (ks * 16 + b_k) * 2);
                LDSM4(bb[2*jj][0], bb[2*jj][1], bb[2*jj+1][0], bb[2*jj+1][1], bd);
            }
#pragma unroll
            for (int i = 0; i < 2; i++)
#pragma unroll
                for (int j = 0; j < 4; j++)
                    MMA(acc[i][j], ah[i], bb[j]);
        }
        __syncthreads();
    }

    int m0 = bm + wm * 32 + (lane >> 2);
    int n0 = bn + wn * 32 + 2 * (lane & 3);
#pragma unroll
    for (int i = 0; i < 2; i++)
#pragma unroll
        for (int j = 0; j < 4; j++) {
            *(float2*)(g_p + (size_t)(m0 + i * 16) * NPAD + n0 + j * 8) =
                make_float2(acc[i][j][0], acc[i][j][1]);
            *(float2*)(g_p + (size_t)(m0 + i * 16 + 8) * NPAD + n0 + j * 8) =
                make_float2(acc[i][j][2], acc[i][j][3]);
        }
}

// ---------------- param transform (+ zero kinematics) ----------------
__device__ __forceinline__ float softplusf(float x) {
    return (x > 20.0f) ? x : log1pf(expf(x));
}

__global__ void transform_kernel(const float* __restrict__ bias, float* __restrict__ out, int seq) {
    int t = blockIdx.x * blockDim.x + threadIdx.x;
    if (t >= seq * NIMU) return;
    int s = t / NIMU, imu = t - s * NIMU;
    float p[12];
#pragma unroll
    for (int n = 0; n < 12; n++)
        p[n] = g_p[(size_t)s * NPAD + n * NIMU + imu] + bias[n * NIMU + imu];

    float d1 = softplusf(p[1]);
    float w1 = sqrtf(softplusf(p[0]));
    float d2 = softplusf(p[3]);
    float w2 = sqrtf(softplusf(p[2]));
    float E1 = expf(-0.5f * d1), E2 = expf(-0.5f * d2);
    float sw1, cw1, sw2, cw2, sp1, cp1, sp2, cp2;
    sincosf(w1, &sw1, &cw1);
    sincosf(w2, &sw2, &cw2);
    sincosf(p[6], &sp1, &cp1);
    sincosf(p[7], &sp2, &cp2);

    float4 u = make_float4(E1 * cw1, E1 * sw1, p[4] * sp1, p[4] * cp1);
    float4 v = make_float4(E2 * cw2, E2 * sw2, p[5] * sp2, p[5] * cp2);
    float4* dst = (float4*)(g_osc + (size_t)t * 8);
    dst[0] = u;
    dst[1] = v;

    size_t SL = (size_t)seq, sec = (size_t)NIMU * SL;
    out[0 * sec + (size_t)imu * SL + s] = 0.0f;
    out[1 * sec + (size_t)imu * SL + s] = p[8];
    out[2 * sec + (size_t)imu * SL + s] = softplusf(p[9]);
    out[3 * sec + (size_t)imu * SL + s] = p[10];
    out[4 * sec + (size_t)imu * SL + s] = softplusf(p[11]);
}

// ---------------- oscillator, packed f32x2, rotating accumulator ----------------
__global__ __launch_bounds__(256) void osc_kernel(float* __restrict__ out, int seq, int tsteps) {
    int chunks = seq >> 8;
    int imu = blockIdx.x / chunks;
    int ch  = blockIdx.x - imu * chunks;
    int lane = threadIdx.x & 31;
    int B = ch * 256 + (threadIdx.x >> 5) * 32;
    int s = B + lane;

    const float4* oc = (const float4*)(g_osc + ((size_t)s * NIMU + imu) * 8);
    float4 u = oc[0], v = oc[1];
    unsigned long long A  = packf2(u.x, v.x);     // a1, a2
    unsigned long long Bc = packf2(u.y, v.y);     // b1, b2
    unsigned long long NB = packf2(-u.y, -v.y);
    unsigned long long S  = packf2(u.z, v.z);     // S1, S2
    unsigned long long C  = packf2(u.w, v.w);     // C1, C2
    unsigned long long accp = 0ull;
    float* kout = out + (size_t)imu * seq;

#pragma unroll 4
    for (int t = 0; t < tsteps; t++) {
        ADDX2(accp, accp, S);
        unsigned long long t1, t2, Sn;
        MULX2(t1, Bc, C);
        MULX2(t2, A, C);
        FMAX2(Sn, A, S, t1);
        FMAX2(C, NB, S, t2);
        S = Sn;
        if (lane == 0) {
            int pos = B + t;
            if (pos < seq) {
                float lo, hi;
                unpackf2(lo, hi, accp);
                atomicAdd(kout + pos, lo + hi);
            }
            accp = 0ull;
        }
        accp = __shfl_sync(0xffffffffu, accp, (lane + 1) & 31);
    }
    int pos = B + tsteps + lane;
    if (pos < seq) {
        float lo, hi;
        unpackf2(lo, hi, accp);
        float a = lo + hi;
        if (a != 0.0f) atomicAdd(kout + pos, a);
    }
}

extern "C" void kernel_launch(void* const* d_in, const int* in_sizes, int n_in,
                              void* d_out, int out_size) {
    const float* x     = (const float*)d_in[0];
    const float* gamma = (const float*)d_in[1];
    const float* beta  = (const float*)d_in[2];
    const float* W     = (const float*)d_in[3];
    const float* b     = (const float*)d_in[4];
    float* out = (float*)d_out;

    int seq = in_sizes[0] / DM;
    int tsteps = seq < 300 ? seq : 300;
    int gemm_smem = 3 * STAGEB;   // 96 KB -> 2 CTAs/SM

    cudaFuncSetAttribute(gemm_kernel, cudaFuncAttributeMaxDynamicSharedMemorySize, gemm_smem);

    ln_kernel<<<seq, 256>>>(x, gamma, beta);
    dim3 wg(DM / 32, NPAD / 32);
    wsplit_kernel<<<wg, 256>>>(W);
    dim3 gg(seq / 128, NPAD / 128);
    gemm_kernel<<<gg, 512, gemm_smem>>>();
    transform_kernel<<<(seq * NIMU + 255) / 256, 256>>>(b, out, seq);
    osc_kernel<<<NIMU * (seq / 256), 256>>>(out, seq, tsteps);
}

// round 10
// speedup vs baseline: 1.0225x; 1.0225x over previous
#include <cuda_runtime.h>
#include <cuda_bf16.h>
#include <math.h>
#include <stdint.h>

#define DM    1024
#define NIMU  72
#define NOUT  864
#define NPAD  896
#define KC2   32
#define NCH2  (DM / KC2)       // 32 chunks
#define ATILE 8192             // 128 rows x 64B
#define STG2B (4 * ATILE)      // Ah, Al, Bh, Bl = 32KB
#define GSMEM (3 * STG2B)      // 96KB -> 2 CTAs/SM

__device__ __nv_bfloat16 g_xn_hi[4096 * DM];
__device__ __nv_bfloat16 g_xn_lo[4096 * DM];
__device__ __nv_bfloat16 g_wT_hi[NPAD * DM];
__device__ __nv_bfloat16 g_wT_lo[NPAD * DM];
__device__ float         g_p[4096 * NPAD];
__device__ float         g_osc[4096 * NIMU * 8];

__device__ __forceinline__ uint32_t smem_u32(const void* p) {
    uint32_t a;
    asm("{ .reg .u64 t; cvta.to.shared.u64 t, %1; cvt.u32.u64 %0, t; }" : "=r"(a) : "l"(p));
    return a;
}
#define SWZ64(o) ((o) ^ (((o) >> 3) & 0x30))

__device__ __forceinline__ void cp16(uint32_t s, const void* g) {
    asm volatile("cp.async.cg.shared.global [%0], [%1], 16;"
                 :: "r"(s), "l"(__cvta_generic_to_global(g)) : "memory");
}
#define CP_COMMIT() asm volatile("cp.async.commit_group;" ::: "memory")
#define CP_WAIT(n)  asm volatile("cp.async.wait_group %0;" :: "n"(n) : "memory")

#define LDSM4(r0, r1, r2, r3, a) \
    asm volatile("ldmatrix.sync.aligned.m8n8.x4.shared.b16 {%0,%1,%2,%3}, [%4];" \
                 : "=r"(r0), "=r"(r1), "=r"(r2), "=r"(r3) : "r"(a))

#define MMA(d, a, b0, b1) \
    asm volatile("mma.sync.aligned.m16n8k16.row.col.f32.bf16.bf16.f32 " \
                 "{%0,%1,%2,%3}, {%4,%5,%6,%7}, {%8,%9}, {%0,%1,%2,%3};" \
                 : "+f"((d)[0]), "+f"((d)[1]), "+f"((d)[2]), "+f"((d)[3]) \
                 : "r"((a)[0]), "r"((a)[1]), "r"((a)[2]), "r"((a)[3]), \
                   "r"(b0), "r"(b1))

// ---------------- fused prep: LayerNorm-split (blocks [0,seq)) + W-split (rest) ----------------
__global__ __launch_bounds__(256) void prep_kernel(const float* __restrict__ x,
                                                   const float* __restrict__ gamma,
                                                   const float* __restrict__ beta,
                                                   const float* __restrict__ W, int seq) {
    if ((int)blockIdx.x < seq) {
        int s = blockIdx.x, tid = threadIdx.x;
        const float4* xr = (const float4*)(x + (size_t)s * DM);
        float4 v = xr[tid];
        float sum = v.x + v.y + v.z + v.w;
        float sq  = v.x*v.x + v.y*v.y + v.z*v.z + v.w*v.w;
#pragma unroll
        for (int o = 16; o > 0; o >>= 1) {
            sum += __shfl_xor_sync(0xffffffffu, sum, o);
            sq  += __shfl_xor_sync(0xffffffffu, sq,  o);
        }
        __shared__ float ssum[8], ssq[8], s_mu, s_rs;
        int wid = tid >> 5, lane = tid & 31;
        if (lane == 0) { ssum[wid] = sum; ssq[wid] = sq; }
        __syncthreads();
        if (tid == 0) {
            float ts = 0.f, tq = 0.f;
#pragma unroll
            for (int i = 0; i < 8; i++) { ts += ssum[i]; tq += ssq[i]; }
            float mu  = ts * (1.0f / DM);
            float var = tq * (1.0f / DM) - mu * mu;
            s_mu = mu; s_rs = rsqrtf(var + 1e-5f);
        }
        __syncthreads();
        float mu = s_mu, rs = s_rs;
        size_t base = (size_t)s * DM + (size_t)tid * 4;
        float xv[4] = {v.x, v.y, v.z, v.w};
#pragma unroll
        for (int j = 0; j < 4; j++) {
            int c = tid * 4 + j;
            float xn = (xv[j] - mu) * rs * gamma[c] + beta[c];
            __nv_bfloat16 hi = __float2bfloat16(xn);
            g_xn_hi[base + j] = hi;
            g_xn_lo[base + j] = __float2bfloat16(xn - __bfloat162float(hi));
        }
    } else {
        __shared__ float tile[32][33];
        int wb = blockIdx.x - seq;
        int k0 = (wb / (NPAD / 32)) * 32, n0 = (wb % (NPAD / 32)) * 32;
        int tx = threadIdx.x & 31, ty = threadIdx.x >> 5;
#pragma unroll
        for (int i = 0; i < 4; i++) {
            int k = k0 + ty + i * 8, n = n0 + tx;
            tile[ty + i * 8][tx] = (n < NOUT) ? W[k * NOUT + n] : 0.0f;
        }
        __syncthreads();
#pragma unroll
        for (int i = 0; i < 4; i++) {
            int n = n0 + ty + i * 8, k = k0 + tx;
            float w = tile[tx][ty + i * 8];
            __nv_bfloat16 hi = __float2bfloat16(w);
            size_t idx = (size_t)n * DM + k;
            g_wT_hi[idx] = hi;
            g_wT_lo[idx] = __float2bfloat16(w - __bfloat162float(hi));
        }
    }
}

// ---------------- 3-split bf16 GEMM, KC=32, 3-stage, 2 CTAs/SM ----------------
__global__ __launch_bounds__(512, 2) void gemm_kernel() {
    extern __shared__ __align__(1024) char smem[];
    uint32_t sb = smem_u32(smem);
    int tid = threadIdx.x, wid = tid >> 5, lane = tid & 31;
    int bm = blockIdx.x * 128, bn = blockIdx.y * 128;
    int wm = wid & 3, wn = wid >> 2;   // 4x4 warps, 32x32 tiles

    // stage loader: 4 tiles x 512 segs; thread loads 1 seg per tile
    int lr = tid >> 2, lc = tid & 3;
    uint32_t lsw = SWZ64(lr * 64 + lc * 16);
    auto load_stage = [&](int kc, int buf) {
        uint32_t base = sb + (uint32_t)buf * STG2B;
        size_t ga = (size_t)(bm + lr) * DM + kc * KC2 + lc * 8;
        size_t gb = (size_t)(bn + lr) * DM + kc * KC2 + lc * 8;
        cp16(base + lsw,             g_xn_hi + ga);
        cp16(base + ATILE + lsw,     g_xn_lo + ga);
        cp16(base + 2 * ATILE + lsw, g_wT_hi + gb);
        cp16(base + 3 * ATILE + lsw, g_wT_lo + gb);
        CP_COMMIT();
    };

    load_stage(0, 0);
    load_stage(1, 1);

    float acc[2][4][4];
#pragma unroll
    for (int i = 0; i < 2; i++)
#pragma unroll
        for (int j = 0; j < 4; j++)
#pragma unroll
            for (int q = 0; q < 4; q++) acc[i][j][q] = 0.0f;

    int a_m = (lane & 7) + ((lane >> 3) & 1) * 8;
    int a_k = (lane >> 4) * 8;
    int b_n = (lane & 7) + ((lane >> 4) & 1) * 8;
    int b_k = ((lane >> 3) & 1) * 8;

    for (int kc = 0; kc < NCH2; kc++) {
        if (kc + 2 < NCH2)       { load_stage(kc + 2, (kc + 2) % 3); CP_WAIT(2); }
        else if (kc + 2 == NCH2) { CP_WAIT(1); }
        else                     { CP_WAIT(0); }
        __syncthreads();
        uint32_t st = sb + (uint32_t)(kc % 3) * STG2B;
#pragma unroll
        for (int ks = 0; ks < 2; ks++) {
            uint32_t ah[2][4], al[2][4];
#pragma unroll
            for (int i = 0; i < 2; i++) {
                uint32_t ad = st + SWZ64((wm * 32 + i * 16 + a_m) * 64 + (ks * 16 + a_k) * 2);
                LDSM4(ah[i][0], ah[i][1], ah[i][2], ah[i][3], ad);
                LDSM4(al[i][0], al[i][1], al[i][2], al[i][3], ad + ATILE);
            }
#pragma unroll
            for (int jj = 0; jj < 2; jj++) {
                uint32_t bd = st + 2 * ATILE +
                              SWZ64((wn * 32 + jj * 16 + b_n) * 64 + (ks * 16 + b_k) * 2);
                {   // Bh pair: hi*Bh + lo*Bh
                    uint32_t b0, b1, b2, b3;
                    LDSM4(b0, b1, b2, b3, bd);
#pragma unroll
                    for (int i = 0; i < 2; i++) {
                        MMA(acc[i][2*jj],   ah[i], b0, b1);
                        MMA(acc[i][2*jj+1], ah[i], b2, b3);
                        MMA(acc[i][2*jj],   al[i], b0, b1);
                        MMA(acc[i][2*jj+1], al[i], b2, b3);
                    }
                }
                {   // Bl pair: hi*Bl
                    uint32_t b0, b1, b2, b3;
                    LDSM4(b0, b1, b2, b3, bd + ATILE);
#pragma unroll
                    for (int i = 0; i < 2; i++) {
                        MMA(acc[i][2*jj],   ah[i], b0, b1);
                        MMA(acc[i][2*jj+1], ah[i], b2, b3);
                    }
                }
            }
        }
        __syncthreads();
    }

    int m0 = bm + wm * 32 + (lane >> 2);
    int n0 = bn + wn * 32 + 2 * (lane & 3);
#pragma unroll
    for (int i = 0; i < 2; i++)
#pragma unroll
        for (int j = 0; j < 4; j++) {
            *(float2*)(g_p + (size_t)(m0 + i * 16) * NPAD + n0 + j * 8) =
                make_float2(acc[i][j][0], acc[i][j][1]);
            *(float2*)(g_p + (size_t)(m0 + i * 16 + 8) * NPAD + n0 + j * 8) =
                make_float2(acc[i][j][2], acc[i][j][3]);
        }
}

// ---------------- param transform, smem-staged coalesced output ----------------
__device__ __forceinline__ float softplusf(float x) {
    return (x > 20.0f) ? x : log1pf(expf(x));
}

__global__ __launch_bounds__(256) void transform_kernel(const float* __restrict__ bias,
                                                        float* __restrict__ out, int seq) {
    __shared__ float stg[5][NIMU][33];
    int s0 = blockIdx.x * 32;

    for (int j = threadIdx.x; j < 32 * NIMU; j += 256) {
        int sl = j / NIMU, imu = j - sl * NIMU;
        int s = s0 + sl;
        float p[12];
#pragma unroll
        for (int n = 0; n < 12; n++)
            p[n] = g_p[(size_t)s * NPAD + n * NIMU + imu] + bias[n * NIMU + imu];

        float d1 = softplusf(p[1]);
        float w1 = sqrtf(softplusf(p[0]));
        float d2 = softplusf(p[3]);
        float w2 = sqrtf(softplusf(p[2]));
        float E1 = expf(-0.5f * d1), E2 = expf(-0.5f * d2);
        float sw1, cw1, sw2, cw2, sp1, cp1, sp2, cp2;
        sincosf(w1, &sw1, &cw1);
        sincosf(w2, &sw2, &cw2);
        sincosf(p[6], &sp1, &cp1);
        sincosf(p[7], &sp2, &cp2);

        size_t t = (size_t)s * NIMU + imu;
        float4* dst = (float4*)(g_osc + t * 8);
        dst[0] = make_float4(E1 * cw1, E1 * sw1, p[4] * sp1, p[4] * cp1);
        dst[1] = make_float4(E2 * cw2, E2 * sw2, p[5] * sp2, p[5] * cp2);

        stg[0][imu][sl] = 0.0f;
        stg[1][imu][sl] = p[8];
        stg[2][imu][sl] = softplusf(p[9]);
        stg[3][imu][sl] = p[10];
        stg[4][imu][sl] = softplusf(p[11]);
    }
    __syncthreads();

    size_t sec = (size_t)NIMU * seq;
    for (int j = threadIdx.x; j < 5 * NIMU * 32; j += 256) {
        int q = j / (NIMU * 32), rem = j - q * NIMU * 32;
        int imu = rem >> 5, sl = rem & 31;
        out[q * sec + (size_t)imu * seq + s0 + sl] = stg[q][imu][sl];
    }
}

// ---------------- oscillator + rotating-accumulator scatter (R7 scalar) ----------------
__global__ __launch_bounds__(256) void osc_kernel(float* __restrict__ out, int seq, int tsteps) {
    int chunks = seq >> 8;
    int imu = blockIdx.x / chunks;
    int ch  = blockIdx.x - imu * chunks;
    int lane = threadIdx.x & 31;
    int B = ch * 256 + (threadIdx.x >> 5) * 32;
    int s = B + lane;

    const float4* oc = (const float4*)(g_osc + ((size_t)s * NIMU + imu) * 8);
    float4 u = oc[0], v = oc[1];
    float a1 = u.x, b1 = u.y, S1 = u.z, C1 = u.w;
    float a2 = v.x, b2 = v.y, S2 = v.z, C2 = v.w;
    float nb1 = -b1, nb2 = -b2;
    float acc = 0.0f;
    float* kout = out + (size_t)imu * seq;

#pragma unroll 4
    for (int t = 0; t < tsteps; t++) {
        acc += S1;
        acc += S2;
        float Sn1 = fmaf(a1, S1, b1 * C1);
        C1 = fmaf(nb1, S1, a1 * C1);
        S1 = Sn1;
        float Sn2 = fmaf(a2, S2, b2 * C2);
        C2 = fmaf(nb2, S2, a2 * C2);
        S2 = Sn2;
        int pos = B + t;
        if (lane == 0) {
            if (pos < seq) atomicAdd(kout + pos, acc);
            acc = 0.0f;
        }
        acc = __shfl_sync(0xffffffffu, acc, (lane + 1) & 31);
    }
    int pos = B + tsteps + lane;
    if (pos < seq && acc != 0.0f) atomicAdd(kout + pos, acc);
}

extern "C" void kernel_launch(void* const* d_in, const int* in_sizes, int n_in,
                              void* d_out, int out_size) {
    const float* x     = (const float*)d_in[0];
    const float* gamma = (const float*)d_in[1];
    const float* beta  = (const float*)d_in[2];
    const float* W     = (const float*)d_in[3];
    const float* b     = (const float*)d_in[4];
    float* out = (float*)d_out;

    int seq = in_sizes[0] / DM;
    int tsteps = seq < 300 ? seq : 300;

    cudaFuncSetAttribute(gemm_kernel, cudaFuncAttributeMaxDynamicSharedMemorySize, GSMEM);

    prep_kernel<<<seq + (DM / 32) * (NPAD / 32), 256>>>(x, gamma, beta, W, seq);
    dim3 gg(seq / 128, NPAD / 128);
    gemm_kernel<<<gg, 512, GSMEM>>>();
    transform_kernel<<<seq / 32, 256>>>(b, out, seq);
    osc_kernel<<<NIMU * (seq / 256), 256>>>(out, seq, tsteps);
}

// round 12
// speedup vs baseline: 1.0575x; 1.0342x over previous
#include <cuda_runtime.h>
#include <cuda_bf16.h>
#include <math.h>
#include <stdint.h>

#define DM    1024
#define NIMU  72
#define NOUT  864
#define NPAD  896
#define KC    64
#define NCH   (DM / KC)
#define TILEB 16384
#define STAGEB (4 * TILEB)

__device__ __nv_bfloat16 g_xn_hi[4096 * DM];
__device__ __nv_bfloat16 g_xn_lo[4096 * DM];
__device__ __nv_bfloat16 g_wT_hi[NPAD * DM];
__device__ __nv_bfloat16 g_wT_lo[NPAD * DM];
__device__ float         g_p[4096 * NPAD];
__device__ float         g_osc[4096 * NIMU * 8];

__device__ __forceinline__ uint32_t smem_u32(const void* p) {
    uint32_t a;
    asm("{ .reg .u64 t; cvta.to.shared.u64 t, %1; cvt.u32.u64 %0, t; }" : "=r"(a) : "l"(p));
    return a;
}
#define SWZ128(o) ((o) ^ (((o) >> 3) & 0x70))

__device__ __forceinline__ void cp16(uint32_t s, const void* g) {
    asm volatile("cp.async.cg.shared.global [%0], [%1], 16;"
                 :: "r"(s), "l"(__cvta_generic_to_global(g)) : "memory");
}
#define CP_COMMIT() asm volatile("cp.async.commit_group;" ::: "memory")
#define CP_WAIT(n)  asm volatile("cp.async.wait_group %0;" :: "n"(n) : "memory")

#define LDSM4(r0, r1, r2, r3, a) \
    asm volatile("ldmatrix.sync.aligned.m8n8.x4.shared.b16 {%0,%1,%2,%3}, [%4];" \
                 : "=r"(r0), "=r"(r1), "=r"(r2), "=r"(r3) : "r"(a))

#define MMA(d, a, b) \
    asm volatile("mma.sync.aligned.m16n8k16.row.col.f32.bf16.bf16.f32 " \
                 "{%0,%1,%2,%3}, {%4,%5,%6,%7}, {%8,%9}, {%0,%1,%2,%3};" \
                 : "+f"((d)[0]), "+f"((d)[1]), "+f"((d)[2]), "+f"((d)[3]) \
                 : "r"((a)[0]), "r"((a)[1]), "r"((a)[2]), "r"((a)[3]), \
                   "r"((b)[0]), "r"((b)[1]))

// packed f32x2 ops (sm_100+)
#define ADDX2(d, a, b) asm("add.rn.f32x2 %0, %1, %2;" : "=l"(d) : "l"(a), "l"(b))
#define MULX2(d, a, b) asm("mul.rn.f32x2 %0, %1, %2;" : "=l"(d) : "l"(a), "l"(b))
#define FMAX2(d, a, b, c) asm("fma.rn.f32x2 %0, %1, %2, %3;" : "=l"(d) : "l"(a), "l"(b), "l"(c))
__device__ __forceinline__ unsigned long long packf2(float lo, float hi) {
    unsigned long long r;
    asm("mov.b64 %0, {%1, %2};" : "=l"(r) : "f"(lo), "f"(hi));
    return r;
}
__device__ __forceinline__ void unpackf2(float& lo, float& hi, unsigned long long v) {
    asm("mov.b64 {%0, %1}, %2;" : "=f"(lo), "=f"(hi) : "l"(v));
}

// ---------------- fused prep: LayerNorm-split (blocks [0,seq)) + W-split (rest) ----------------
__global__ __launch_bounds__(256) void prep_kernel(const float* __restrict__ x,
                                                   const float* __restrict__ gamma,
                                                   const float* __restrict__ beta,
                                                   const float* __restrict__ W, int seq) {
    if ((int)blockIdx.x < seq) {
        int s = blockIdx.x, tid = threadIdx.x;
        const float4* xr = (const float4*)(x + (size_t)s * DM);
        float4 v = xr[tid];
        float sum = v.x + v.y + v.z + v.w;
        float sq  = v.x*v.x + v.y*v.y + v.z*v.z + v.w*v.w;
#pragma unroll
        for (int o = 16; o > 0; o >>= 1) {
            sum += __shfl_xor_sync(0xffffffffu, sum, o);
            sq  += __shfl_xor_sync(0xffffffffu, sq,  o);
        }
        __shared__ float ssum[8], ssq[8], s_mu, s_rs;
        int wid = tid >> 5, lane = tid & 31;
        if (lane == 0) { ssum[wid] = sum; ssq[wid] = sq; }
        __syncthreads();
        if (tid == 0) {
            float ts = 0.f, tq = 0.f;
#pragma unroll
            for (int i = 0; i < 8; i++) { ts += ssum[i]; tq += ssq[i]; }
            float mu  = ts * (1.0f / DM);
            float var = tq * (1.0f / DM) - mu * mu;
            s_mu = mu; s_rs = rsqrtf(var + 1e-5f);
        }
        __syncthreads();
        float mu = s_mu, rs = s_rs;
        size_t base = (size_t)s * DM + (size_t)tid * 4;
        float xv[4] = {v.x, v.y, v.z, v.w};
#pragma unroll
        for (int j = 0; j < 4; j++) {
            int c = tid * 4 + j;
            float xn = (xv[j] - mu) * rs * gamma[c] + beta[c];
            __nv_bfloat16 hi = __float2bfloat16(xn);
            g_xn_hi[base + j] = hi;
            g_xn_lo[base + j] = __float2bfloat16(xn - __bfloat162float(hi));
        }
    } else {
        __shared__ float tile[32][33];
        int wb = blockIdx.x - seq;
        int k0 = (wb / (NPAD / 32)) * 32, n0 = (wb % (NPAD / 32)) * 32;
        int tx = threadIdx.x & 31, ty = threadIdx.x >> 5;
#pragma unroll
        for (int i = 0; i < 4; i++) {
            int k = k0 + ty + i * 8, n = n0 + tx;
            tile[ty + i * 8][tx] = (n < NOUT) ? W[k * NOUT + n] : 0.0f;
        }
        __syncthreads();
#pragma unroll
        for (int i = 0; i < 4; i++) {
            int n = n0 + ty + i * 8, k = k0 + tx;
            float w = tile[tx][ty + i * 8];
            __nv_bfloat16 hi = __float2bfloat16(w);
            size_t idx = (size_t)n * DM + k;
            g_wT_hi[idx] = hi;
            g_wT_lo[idx] = __float2bfloat16(w - __bfloat162float(hi));
        }
    }
}

// ---------------- mma.sync 3-split bf16 GEMM, R7 config: KC=64, 2x64KB stages, 512 thr ----------------
#define LOAD_STAGE(kc, s) do {                                          \
    uint32_t base_ = sb + (uint32_t)(s) * STAGEB;                       \
    _Pragma("unroll")                                                   \
    for (int i_ = 0; i_ < 2; i_++) {                                    \
        int seg_ = tid + i_ * 512;                                      \
        int rr_ = seg_ >> 3, cc_ = seg_ & 7;                            \
        uint32_t sw_ = SWZ128(rr_ * 128 + cc_ * 16);                    \
        size_t ga_ = (size_t)(bm + rr_) * DM + (kc) * KC + cc_ * 8;     \
        size_t gb_ = (size_t)(bn + rr_) * DM + (kc) * KC + cc_ * 8;     \
        cp16(base_ + sw_,             g_xn_hi + ga_);                   \
        cp16(base_ + 16384 + sw_,     g_xn_lo + ga_);                   \
        cp16(base_ + 32768 + sw_,     g_wT_hi + gb_);                   \
        cp16(base_ + 49152 + sw_,     g_wT_lo + gb_);                   \
    }                                                                   \
    CP_COMMIT();                                                        \
} while (0)

__global__ __launch_bounds__(512) void gemm_kernel() {
    extern __shared__ __align__(1024) char smem[];
    uint32_t sb = smem_u32(smem);
    int tid = threadIdx.x, wid = tid >> 5, lane = tid & 31;
    int bm = blockIdx.x * 128, bn = blockIdx.y * 128;
    int wm = wid & 3, wn = wid >> 2;   // 4x4 warp grid, 32x32 warp tiles

    LOAD_STAGE(0, 0);

    float acc[2][4][4];
#pragma unroll
    for (int i = 0; i < 2; i++)
#pragma unroll
        for (int j = 0; j < 4; j++)
#pragma unroll
            for (int q = 0; q < 4; q++) acc[i][j][q] = 0.0f;

    int a_m = (lane & 7) + ((lane >> 3) & 1) * 8;
    int a_k = (lane >> 4) * 8;
    int b_n = (lane & 7) + ((lane >> 4) & 1) * 8;
    int b_k = ((lane >> 3) & 1) * 8;

    for (int kc = 0; kc < NCH; kc++) {
        if (kc + 1 < NCH) { LOAD_STAGE(kc + 1, (kc + 1) & 1); CP_WAIT(1); }
        else              { CP_WAIT(0); }
        __syncthreads();
        uint32_t st = sb + (uint32_t)(kc & 1) * STAGEB;
#pragma unroll
        for (int ks = 0; ks < 4; ks++) {
            uint32_t ah[2][4], al[2][4], bh[4][2], bl[4][2];
#pragma unroll
            for (int i = 0; i < 2; i++) {
                uint32_t ad = st + SWZ128((wm * 32 + i * 16 + a_m) * 128 + (ks * 16 + a_k) * 2);
                LDSM4(ah[i][0], ah[i][1], ah[i][2], ah[i][3], ad);
                LDSM4(al[i][0], al[i][1], al[i][2], al[i][3], ad + 16384);
            }
#pragma unroll
            for (int jj = 0; jj < 2; jj++) {
                uint32_t bd = st + 32768 + SWZ128((wn * 32 + jj * 16 + b_n) * 128 + (ks * 16 + b_k) * 2);
                LDSM4(bh[2*jj][0], bh[2*jj][1], bh[2*jj+1][0], bh[2*jj+1][1], bd);
                LDSM4(bl[2*jj][0], bl[2*jj][1], bl[2*jj+1][0], bl[2*jj+1][1], bd + 16384);
            }
#pragma unroll
            for (int i = 0; i < 2; i++)
#pragma unroll
                for (int j = 0; j < 4; j++) {
                    MMA(acc[i][j], ah[i], bh[j]);
                    MMA(acc[i][j], ah[i], bl[j]);
                    MMA(acc[i][j], al[i], bh[j]);
                }
        }
        __syncthreads();
    }

    int m0 = bm + wm * 32 + (lane >> 2);
    int n0 = bn + wn * 32 + 2 * (lane & 3);
#pragma unroll
    for (int i = 0; i < 2; i++)
#pragma unroll
        for (int j = 0; j < 4; j++) {
            *(float2*)(g_p + (size_t)(m0 + i * 16) * NPAD + n0 + j * 8) =
                make_float2(acc[i][j][0], acc[i][j][1]);
            *(float2*)(g_p + (size_t)(m0 + i * 16 + 8) * NPAD + n0 + j * 8) =
                make_float2(acc[i][j][2], acc[i][j][3]);
        }
}

// ---------------- param transform, smem-staged coalesced output ----------------
__device__ __forceinline__ float softplusf(float x) {
    return (x > 20.0f) ? x : log1pf(expf(x));
}

__global__ __launch_bounds__(256) void transform_kernel(const float* __restrict__ bias,
                                                        float* __restrict__ out, int seq) {
    __shared__ float stg[5][NIMU][33];
    int s0 = blockIdx.x * 32;

    for (int j = threadIdx.x; j < 32 * NIMU; j += 256) {
        int sl = j / NIMU, imu = j - sl * NIMU;
        int s = s0 + sl;
        float p[12];
#pragma unroll
        for (int n = 0; n < 12; n++)
            p[n] = g_p[(size_t)s * NPAD + n * NIMU + imu] + bias[n * NIMU + imu];

        float d1 = softplusf(p[1]);
        float w1 = sqrtf(softplusf(p[0]));
        float d2 = softplusf(p[3]);
        float w2 = sqrtf(softplusf(p[2]));
        float E1 = expf(-0.5f * d1), E2 = expf(-0.5f * d2);
        float sw1, cw1, sw2, cw2, sp1, cp1, sp2, cp2;
        sincosf(w1, &sw1, &cw1);
        sincosf(w2, &sw2, &cw2);
        sincosf(p[6], &sp1, &cp1);
        sincosf(p[7], &sp2, &cp2);

        size_t t = (size_t)s * NIMU + imu;
        float4* dst = (float4*)(g_osc + t * 8);
        dst[0] = make_float4(E1 * cw1, E1 * sw1, p[4] * sp1, p[4] * cp1);
        dst[1] = make_float4(E2 * cw2, E2 * sw2, p[5] * sp2, p[5] * cp2);

        stg[0][imu][sl] = 0.0f;
        stg[1][imu][sl] = p[8];
        stg[2][imu][sl] = softplusf(p[9]);
        stg[3][imu][sl] = p[10];
        stg[4][imu][sl] = softplusf(p[11]);
    }
    __syncthreads();

    size_t sec = (size_t)NIMU * seq;
    for (int j = threadIdx.x; j < 5 * NIMU * 32; j += 256) {
        int q = j / (NIMU * 32), rem = j - q * NIMU * 32;
        int imu = rem >> 5, sl = rem & 31;
        out[q * sec + (size_t)imu * seq + s0 + sl] = stg[q][imu][sl];
    }
}

// ---------------- oscillator, packed f32x2, rotating accumulator ----------------
__global__ __launch_bounds__(128) void osc_kernel(float* __restrict__ out, int seq, int tsteps) {
    int chunks = seq >> 7;
    int imu = blockIdx.x / chunks;
    int ch  = blockIdx.x - imu * chunks;
    int lane = threadIdx.x & 31;
    int B = ch * 128 + (threadIdx.x >> 5) * 32;
    int s = B + lane;

    const float4* oc = (const float4*)(g_osc + ((size_t)s * NIMU + imu) * 8);
    float4 u = oc[0], v = oc[1];
    unsigned long long A  = packf2(u.x, v.x);
    unsigned long long Bc = packf2(u.y, v.y);
    unsigned long long NB = packf2(-u.y, -v.y);
    unsigned long long S  = packf2(u.z, v.z);
    unsigned long long C  = packf2(u.w, v.w);
    unsigned long long accp = 0ull;
    float* kout = out + (size_t)imu * seq;

#pragma unroll 4
    for (int t = 0; t < tsteps; t++) {
        ADDX2(accp, accp, S);
        unsigned long long t1, t2, Sn;
        MULX2(t1, Bc, C);
        MULX2(t2, A, C);
        FMAX2(Sn, A, S, t1);
        FMAX2(C, NB, S, t2);
        S = Sn;
        if (lane == 0) {
            int pos = B + t;
            if (pos < seq) {
                float lo, hi;
                unpackf2(lo, hi, accp);
                atomicAdd(kout + pos, lo + hi);
            }
        }
        accp = __shfl_sync(0xffffffffu, accp, (lane + 1) & 31);
        if (lane == 31) accp = 0ull;   // lane 31 received the retired slot
    }
    int pos = B + tsteps + lane;
    if (pos < seq) {
        float lo, hi;
        unpackf2(lo, hi, accp);
        float a = lo + hi;
        if (a != 0.0f) atomicAdd(kout + pos, a);
    }
}

extern "C" void kernel_launch(void* const* d_in, const int* in_sizes, int n_in,
                              void* d_out, int out_size) {
    const float* x     = (const float*)d_in[0];
    const float* gamma = (const float*)d_in[1];
    const float* beta  = (const float*)d_in[2];
    const float* W     = (const float*)d_in[3];
    const float* b     = (const float*)d_in[4];
    float* out = (float*)d_out;

    int seq = in_sizes[0] / DM;
    int tsteps = seq < 300 ? seq : 300;
    int gemm_smem = 2 * STAGEB;   // 128 KB

    cudaFuncSetAttribute(gemm_kernel, cudaFuncAttributeMaxDynamicSharedMemorySize, gemm_smem);

    prep_kernel<<<seq + (DM / 32) * (NPAD / 32), 256>>>(x, gamma, beta, W, seq);
    dim3 gg(seq / 128, NPAD / 128);
    gemm_kernel<<<gg, 512, gemm_smem>>>();
    transform_kernel<<<seq / 32, 256>>>(b, out, seq);
    osc_kernel<<<NIMU * (seq / 128), 128>>>(out, seq, tsteps);
}

// round 13
// speedup vs baseline: 1.1495x; 1.0870x over previous
#include <cuda_runtime.h>
#include <cuda_bf16.h>
#include <math.h>
#include <stdint.h>

#define DM    1024
#define NIMU  72
#define NOUT  864
#define NPAD  896
#define KC    64
#define NCH   (DM / KC)
#define TILEB 16384
#define STAGEB (4 * TILEB)

__device__ __nv_bfloat16 g_xn_hi[4096 * DM];
__device__ __nv_bfloat16 g_xn_lo[4096 * DM];
__device__ __nv_bfloat16 g_wT_hi[NPAD * DM];
__device__ __nv_bfloat16 g_wT_lo[NPAD * DM];
__device__ float         g_p[4096 * NPAD];
__device__ float         g_osc[4096 * NIMU * 8];

__device__ __forceinline__ uint32_t smem_u32(const void* p) {
    uint32_t a;
    asm("{ .reg .u64 t; cvta.to.shared.u64 t, %1; cvt.u32.u64 %0, t; }" : "=r"(a) : "l"(p));
    return a;
}
#define SWZ128(o) ((o) ^ (((o) >> 3) & 0x70))

__device__ __forceinline__ void cp16(uint32_t s, const void* g) {
    asm volatile("cp.async.cg.shared.global [%0], [%1], 16;"
                 :: "r"(s), "l"(__cvta_generic_to_global(g)) : "memory");
}
#define CP_COMMIT() asm volatile("cp.async.commit_group;" ::: "memory")
#define CP_WAIT(n)  asm volatile("cp.async.wait_group %0;" :: "n"(n) : "memory")

#define LDSM4(r0, r1, r2, r3, a) \
    asm volatile("ldmatrix.sync.aligned.m8n8.x4.shared.b16 {%0,%1,%2,%3}, [%4];" \
                 : "=r"(r0), "=r"(r1), "=r"(r2), "=r"(r3) : "r"(a))

#define MMA(d, a, b) \
    asm volatile("mma.sync.aligned.m16n8k16.row.col.f32.bf16.bf16.f32 " \
                 "{%0,%1,%2,%3}, {%4,%5,%6,%7}, {%8,%9}, {%0,%1,%2,%3};" \
                 : "+f"((d)[0]), "+f"((d)[1]), "+f"((d)[2]), "+f"((d)[3]) \
                 : "r"((a)[0]), "r"((a)[1]), "r"((a)[2]), "r"((a)[3]), \
                   "r"((b)[0]), "r"((b)[1]))

// packed f32x2 ops (sm_100+)
#define MULX2(d, a, b) asm("mul.rn.f32x2 %0, %1, %2;" : "=l"(d) : "l"(a), "l"(b))
#define FMAX2(d, a, b, c) asm("fma.rn.f32x2 %0, %1, %2, %3;" : "=l"(d) : "l"(a), "l"(b), "l"(c))
__device__ __forceinline__ unsigned long long packf2(float lo, float hi) {
    unsigned long long r;
    asm("mov.b64 %0, {%1, %2};" : "=l"(r) : "f"(lo), "f"(hi));
    return r;
}
__device__ __forceinline__ void unpackf2(float& lo, float& hi, unsigned long long v) {
    asm("mov.b64 {%0, %1}, %2;" : "=f"(lo), "=f"(hi) : "l"(v));
}

// ---------------- fused prep: LayerNorm-split (blocks [0,seq)) + W-split (rest) ----------------
__global__ __launch_bounds__(256) void prep_kernel(const float* __restrict__ x,
                                                   const float* __restrict__ gamma,
                                                   const float* __restrict__ beta,
                                                   const float* __restrict__ W, int seq) {
    if ((int)blockIdx.x < seq) {
        int s = blockIdx.x, tid = threadIdx.x;
        const float4* xr = (const float4*)(x + (size_t)s * DM);
        float4 v = xr[tid];
        float sum = v.x + v.y + v.z + v.w;
        float sq  = v.x*v.x + v.y*v.y + v.z*v.z + v.w*v.w;
#pragma unroll
        for (int o = 16; o > 0; o >>= 1) {
            sum += __shfl_xor_sync(0xffffffffu, sum, o);
            sq  += __shfl_xor_sync(0xffffffffu, sq,  o);
        }
        __shared__ float ssum[8], ssq[8], s_mu, s_rs;
        int wid = tid >> 5, lane = tid & 31;
        if (lane == 0) { ssum[wid] = sum; ssq[wid] = sq; }
        __syncthreads();
        if (tid == 0) {
            float ts = 0.f, tq = 0.f;
#pragma unroll
            for (int i = 0; i < 8; i++) { ts += ssum[i]; tq += ssq[i]; }
            float mu  = ts * (1.0f / DM);
            float var = tq * (1.0f / DM) - mu * mu;
            s_mu = mu; s_rs = rsqrtf(var + 1e-5f);
        }
        __syncthreads();
        float mu = s_mu, rs = s_rs;
        size_t base = (size_t)s * DM + (size_t)tid * 4;
        float xv[4] = {v.x, v.y, v.z, v.w};
#pragma unroll
        for (int j = 0; j < 4; j++) {
            int c = tid * 4 + j;
            float xn = (xv[j] - mu) * rs * gamma[c] + beta[c];
            __nv_bfloat16 hi = __float2bfloat16(xn);
            g_xn_hi[base + j] = hi;
            g_xn_lo[base + j] = __float2bfloat16(xn - __bfloat162float(hi));
        }
    } else {
        __shared__ float tile[32][33];
        int wb = blockIdx.x - seq;
        int k0 = (wb / (NPAD / 32)) * 32, n0 = (wb % (NPAD / 32)) * 32;
        int tx = threadIdx.x & 31, ty = threadIdx.x >> 5;
#pragma unroll
        for (int i = 0; i < 4; i++) {
            int k = k0 + ty + i * 8, n = n0 + tx;
            tile[ty + i * 8][tx] = (n < NOUT) ? W[k * NOUT + n] : 0.0f;
        }
        __syncthreads();
#pragma unroll
        for (int i = 0; i < 4; i++) {
            int n = n0 + ty + i * 8, k = k0 + tx;
            float w = tile[tx][ty + i * 8];
            __nv_bfloat16 hi = __float2bfloat16(w);
            size_t idx = (size_t)n * DM + k;
            g_wT_hi[idx] = hi;
            g_wT_lo[idx] = __float2bfloat16(w - __bfloat162float(hi));
        }
    }
}

// ---------------- mma.sync 3-split bf16 GEMM (R7 config) ----------------
#define LOAD_STAGE(kc, s) do {                                          \
    uint32_t base_ = sb + (uint32_t)(s) * STAGEB;                       \
    _Pragma("unroll")                                                   \
    for (int i_ = 0; i_ < 2; i_++) {                                    \
        int seg_ = tid + i_ * 512;                                      \
        int rr_ = seg_ >> 3, cc_ = seg_ & 7;                            \
        uint32_t sw_ = SWZ128(rr_ * 128 + cc_ * 16);                    \
        size_t ga_ = (size_t)(bm + rr_) * DM + (kc) * KC + cc_ * 8;     \
        size_t gb_ = (size_t)(bn + rr_) * DM + (kc) * KC + cc_ * 8;     \
        cp16(base_ + sw_,             g_xn_hi + ga_);                   \
        cp16(base_ + 16384 + sw_,     g_xn_lo + ga_);                   \
        cp16(base_ + 32768 + sw_,     g_wT_hi + gb_);                   \
        cp16(base_ + 49152 + sw_,     g_wT_lo + gb_);                   \
    }                                                                   \
    CP_COMMIT();                                                        \
} while (0)

__global__ __launch_bounds__(512) void gemm_kernel() {
    extern __shared__ __align__(1024) char smem[];
    uint32_t sb = smem_u32(smem);
    int tid = threadIdx.x, wid = tid >> 5, lane = tid & 31;
    int bm = blockIdx.x * 128, bn = blockIdx.y * 128;
    int wm = wid & 3, wn = wid >> 2;

    LOAD_STAGE(0, 0);

    float acc[2][4][4];
#pragma unroll
    for (int i = 0; i < 2; i++)
#pragma unroll
        for (int j = 0; j < 4; j++)
#pragma unroll
            for (int q = 0; q < 4; q++) acc[i][j][q] = 0.0f;

    int a_m = (lane & 7) + ((lane >> 3) & 1) * 8;
    int a_k = (lane >> 4) * 8;
    int b_n = (lane & 7) + ((lane >> 4) & 1) * 8;
    int b_k = ((lane >> 3) & 1) * 8;

    for (int kc = 0; kc < NCH; kc++) {
        if (kc + 1 < NCH) { LOAD_STAGE(kc + 1, (kc + 1) & 1); CP_WAIT(1); }
        else              { CP_WAIT(0); }
        __syncthreads();
        uint32_t st = sb + (uint32_t)(kc & 1) * STAGEB;
#pragma unroll
        for (int ks = 0; ks < 4; ks++) {
            uint32_t ah[2][4], al[2][4], bh[4][2], bl[4][2];
#pragma unroll
            for (int i = 0; i < 2; i++) {
                uint32_t ad = st + SWZ128((wm * 32 + i * 16 + a_m) * 128 + (ks * 16 + a_k) * 2);
                LDSM4(ah[i][0], ah[i][1], ah[i][2], ah[i][3], ad);
                LDSM4(al[i][0], al[i][1], al[i][2], al[i][3], ad + 16384);
            }
#pragma unroll
            for (int jj = 0; jj < 2; jj++) {
                uint32_t bd = st + 32768 + SWZ128((wn * 32 + jj * 16 + b_n) * 128 + (ks * 16 + b_k) * 2);
                LDSM4(bh[2*jj][0], bh[2*jj][1], bh[2*jj+1][0], bh[2*jj+1][1], bd);
                LDSM4(bl[2*jj][0], bl[2*jj][1], bl[2*jj+1][0], bl[2*jj+1][1], bd + 16384);
            }
#pragma unroll
            for (int i = 0; i < 2; i++)
#pragma unroll
                for (int j = 0; j < 4; j++) {
                    MMA(acc[i][j], ah[i], bh[j]);
                    MMA(acc[i][j], ah[i], bl[j]);
                    MMA(acc[i][j], al[i], bh[j]);
                }
        }
        __syncthreads();
    }

    int m0 = bm + wm * 32 + (lane >> 2);
    int n0 = bn + wn * 32 + 2 * (lane & 3);
#pragma unroll
    for (int i = 0; i < 2; i++)
#pragma unroll
        for (int j = 0; j < 4; j++) {
            *(float2*)(g_p + (size_t)(m0 + i * 16) * NPAD + n0 + j * 8) =
                make_float2(acc[i][j][0], acc[i][j][1]);
            *(float2*)(g_p + (size_t)(m0 + i * 16 + 8) * NPAD + n0 + j * 8) =
                make_float2(acc[i][j][2], acc[i][j][3]);
        }
}

// ---------------- param transform, smem-staged coalesced output ----------------
__device__ __forceinline__ float softplusf(float x) {
    return (x > 20.0f) ? x : log1pf(expf(x));
}

__global__ __launch_bounds__(256) void transform_kernel(const float* __restrict__ bias,
                                                        float* __restrict__ out, int seq) {
    __shared__ float stg[5][NIMU][33];
    int s0 = blockIdx.x * 32;

    for (int j = threadIdx.x; j < 32 * NIMU; j += 256) {
        int sl = j / NIMU, imu = j - sl * NIMU;
        int s = s0 + sl;
        float p[12];
#pragma unroll
        for (int n = 0; n < 12; n++)
            p[n] = g_p[(size_t)s * NPAD + n * NIMU + imu] + bias[n * NIMU + imu];

        float d1 = softplusf(p[1]);
        float w1 = sqrtf(softplusf(p[0]));
        float d2 = softplusf(p[3]);
        float w2 = sqrtf(softplusf(p[2]));
        float E1 = expf(-0.5f * d1), E2 = expf(-0.5f * d2);
        float sw1, cw1, sw2, cw2, sp1, cp1, sp2, cp2;
        sincosf(w1, &sw1, &cw1);
        sincosf(w2, &sw2, &cw2);
        sincosf(p[6], &sp1, &cp1);
        sincosf(p[7], &sp2, &cp2);

        size_t t = (size_t)s * NIMU + imu;
        float4* dst = (float4*)(g_osc + t * 8);
        dst[0] = make_float4(E1 * cw1, E1 * sw1, p[4] * sp1, p[4] * cp1);
        dst[1] = make_float4(E2 * cw2, E2 * sw2, p[5] * sp2, p[5] * cp2);

        stg[0][imu][sl] = 0.0f;
        stg[1][imu][sl] = p[8];
        stg[2][imu][sl] = softplusf(p[9]);
        stg[3][imu][sl] = p[10];
        stg[4][imu][sl] = softplusf(p[11]);
    }
    __syncthreads();

    size_t sec = (size_t)NIMU * seq;
    for (int j = threadIdx.x; j < 5 * NIMU * 32; j += 256) {
        int q = j / (NIMU * 32), rem = j - q * NIMU * 32;
        int imu = rem >> 5, sl = rem & 31;
        out[q * sec + (size_t)imu * seq + s0 + sl] = stg[q][imu][sl];
    }
}

// ---------------- oscillator: packed state, scalar accumulator ----------------
#define OSC_STEP_CORE                                          \
    {                                                          \
        float slo, shi;                                        \
        unpackf2(slo, shi, S);                                 \
        acc += slo;                                            \
        acc += shi;                                            \
        unsigned long long t1, t2, Sn;                         \
        MULX2(t1, Bc, C);                                      \
        MULX2(t2, A, C);                                       \
        FMAX2(Sn, A, S, t1);                                   \
        FMAX2(C, NB, S, t2);                                   \
        S = Sn;                                                \
    }

__global__ __launch_bounds__(256) void osc_kernel(float* __restrict__ out, int seq, int tsteps) {
    int chunks = seq >> 8;
    int imu = blockIdx.x / chunks;
    int ch  = blockIdx.x - imu * chunks;
    int lane = threadIdx.x & 31;
    int B = ch * 256 + (threadIdx.x >> 5) * 32;
    int s = B + lane;

    const float4* oc = (const float4*)(g_osc + ((size_t)s * NIMU + imu) * 8);
    float4 u = oc[0], v = oc[1];
    unsigned long long A  = packf2(u.x, v.x);
    unsigned long long Bc = packf2(u.y, v.y);
    unsigned long long NB = packf2(-u.y, -v.y);
    unsigned long long S  = packf2(u.z, v.z);
    unsigned long long C  = packf2(u.w, v.w);
    float acc = 0.0f;
    float* kout = out + (size_t)imu * seq;
    bool lane0 = (lane == 0);
    float* rbase = kout + B;    // retire address base; lane0 only uses it

    if (B + tsteps <= seq) {
        // interior: no bounds check in loop
#pragma unroll 4
        for (int t = 0; t < tsteps; t++) {
            OSC_STEP_CORE
            if (lane0) { atomicAdd(rbase + t, acc); acc = 0.0f; }
            acc = __shfl_sync(0xffffffffu, acc, (lane + 1) & 31);
        }
    } else {
#pragma unroll 4
        for (int t = 0; t < tsteps; t++) {
            OSC_STEP_CORE
            if (lane0) {
                if (B + t < seq) atomicAdd(rbase + t, acc);
                acc = 0.0f;
            }
            acc = __shfl_sync(0xffffffffu, acc, (lane + 1) & 31);
        }
    }
    int pos = B + tsteps + lane;
    if (pos < seq && acc != 0.0f) atomicAdd(kout + pos, acc);
}

extern "C" void kernel_launch(void* const* d_in, const int* in_sizes, int n_in,
                              void* d_out, int out_size) {
    const float* x     = (const float*)d_in[0];
    const float* gamma = (const float*)d_in[1];
    const float* beta  = (const float*)d_in[2];
    const float* W     = (const float*)d_in[3];
    const float* b     = (const float*)d_in[4];
    float* out = (float*)d_out;

    int seq = in_sizes[0] / DM;
    int tsteps = seq < 300 ? seq : 300;
    int gemm_smem = 2 * STAGEB;   // 128 KB

    cudaFuncSetAttribute(gemm_kernel, cudaFuncAttributeMaxDynamicSharedMemorySize, gemm_smem);

    prep_kernel<<<seq + (DM / 32) * (NPAD / 32), 256>>>(x, gamma, beta, W, seq);
    dim3 gg(seq / 128, NPAD / 128);
    gemm_kernel<<<gg, 512, gemm_smem>>>();
    transform_kernel<<<seq / 32, 256>>>(b, out, seq);
    osc_kernel<<<NIMU * (seq / 256), 256>>>(out, seq, tsteps);
}